// round 15
// baseline (speedup 1.0000x reference)
#include <cuda_runtime.h>
#include <cuda_bf16.h>
#include <cstdint>

#define EPS 1e-5f

#define BX 8
#define CCH 512
#define KCODES 32
#define NPIX 16384   // 128*128

// ---------------- device scratch ----------------
__device__ __nv_bfloat16 g_feat[(size_t)BX * NPIX * CCH];  // bf16 feat, 134MB
__device__ float g_wr[CCH * CCH];                   // tf32 w, k-pair-permuted layout
__device__ uint2 g_cwfH[4096];                      // bf16 cw B-fragment table
__device__ float g_x2[BX * NPIX];                   // per-pixel |feat|^2 (bf16 vals)
__device__ float g_c2[KCODES];                      // |cw_bf16|^2
__device__ float g_enc[BX * KCODES * CCH];          // [B][K][C]
__device__ float g_awsum[BX * KCODES];              // [B][K]
__device__ float g_encfeat[BX * CCH];               // [B][C]
__device__ float g_gamma1p[BX * CCH];               // 1 + sigmoid(...)

// ---------------- helpers ----------------
__device__ __forceinline__ uint32_t smem_u32(const void* p) {
    uint32_t a;
    asm("{ .reg .u64 t; cvta.to.shared.u64 t, %1; cvt.u32.u64 %0, t; }" : "=r"(a) : "l"(p));
    return a;
}
__device__ __forceinline__ unsigned tf32r(float v) {
    unsigned u; asm("cvt.rna.tf32.f32 %0, %1;" : "=r"(u) : "f"(v)); return u;
}
__device__ __forceinline__ float tf32f(float v) { return __uint_as_float(tf32r(v)); }
#define CP16(dst, src) \
    asm volatile("cp.async.cg.shared.global [%0], [%1], 16;" :: "r"(dst), "l"(src))
#define CPCOMMIT() asm volatile("cp.async.commit_group;" ::: "memory")
#define CPWAIT0()  asm volatile("cp.async.wait_group 0;" ::: "memory")
#define CPWAITN(n) asm volatile("cp.async.wait_group %0;" :: "n"(n) : "memory")

__device__ __forceinline__ void mma_tf32(float* c, const unsigned* a, const unsigned* b) {
    asm volatile("mma.sync.aligned.m16n8k8.row.col.f32.tf32.tf32.f32 "
        "{%0,%1,%2,%3}, {%4,%5,%6,%7}, {%8,%9}, {%0,%1,%2,%3};"
        : "+f"(c[0]), "+f"(c[1]), "+f"(c[2]), "+f"(c[3])
        : "r"(a[0]), "r"(a[1]), "r"(a[2]), "r"(a[3]), "r"(b[0]), "r"(b[1]));
}
__device__ __forceinline__ void mma_bf16(float* c, const unsigned* a, const unsigned* b) {
    asm volatile("mma.sync.aligned.m16n8k16.row.col.f32.bf16.bf16.f32 "
        "{%0,%1,%2,%3}, {%4,%5,%6,%7}, {%8,%9}, {%0,%1,%2,%3};"
        : "+f"(c[0]), "+f"(c[1]), "+f"(c[2]), "+f"(c[3])
        : "r"(a[0]), "r"(a[1]), "r"(a[2]), "r"(a[3]), "r"(b[0]), "r"(b[1]));
}
#define LDMX2T(r0, r1, addr) \
    asm volatile("ldmatrix.sync.aligned.m8n8.x2.trans.shared.b16 {%0,%1}, [%2];" \
        : "=r"(r0), "=r"(r1) : "r"(addr))

__device__ __forceinline__ unsigned bf2pack(float a, float b) {
    __nv_bfloat162 h = __floats2bfloat162_rn(a, b);
    return *(unsigned*)&h;
}

// ---------------- K0: zero accumulators ----------------
__global__ void k_zero() {
    int i = blockIdx.x * 256 + threadIdx.x;
    if (i < BX * KCODES * CCH) g_enc[i] = 0.f;
    if (i < BX * NPIX) g_x2[i] = 0.f;
    if (i < BX * KCODES) g_awsum[i] = 0.f;
}

// ---------------- Kpre: tf32-round w, k-pair-permuted storage ----------------
// Within each 8-element k-group, storage s holds global k = (s>>1) + (s&1)*4,
// so the MMA B-frag pair (k, k+4) sits at adjacent words -> LDS.64.
__global__ void k_pre(const float* __restrict__ w)
{
    int i = blockIdx.x * 256 + threadIdx.x;   // 8-group index, 32768 total
    const float* src = w + (size_t)i * 8;
    float4 a = *(const float4*)src;        // global k 0..3
    float4 b = *(const float4*)(src + 4);  // global k 4..7
    float4 o0, o1;
    o0.x = tf32f(a.x); o0.y = tf32f(b.x);  // storage 0,1 = k0,k4
    o0.z = tf32f(a.y); o0.w = tf32f(b.y);  // storage 2,3 = k1,k5
    o1.x = tf32f(a.z); o1.y = tf32f(b.z);  // storage 4,5 = k2,k6
    o1.z = tf32f(a.w); o1.w = tf32f(b.w);  // storage 6,7 = k3,k7
    *(float4*)(g_wr + (size_t)i * 8)     = o0;
    *(float4*)(g_wr + (size_t)i * 8 + 4) = o1;
}

// ---------------- Kcwprep: merged cw frag table + |cw|^2 ----------------
__global__ void k_cwprep(const float* __restrict__ cw) {
    if (blockIdx.x < 16) {
        int p = blockIdx.x * 256 + threadIdx.x;   // 4096
        int lane = p & 31;
        int j    = (p >> 5) & 3;
        int kk   = p >> 7;
        int code = j * 8 + (lane >> 2);
        int k = kk * 16 + 2 * (lane & 3);
        const float* cr = cw + code * CCH + k;
        uint2 v;
        v.x = bf2pack(cr[0], cr[1]);
        v.y = bf2pack(cr[8], cr[9]);
        g_cwfH[p] = v;
    } else {
        int code = threadIdx.x >> 3;
        int s = threadIdx.x & 7;
        float sum = 0.f;
#pragma unroll
        for (int j = 0; j < 64; j++) {
            float v = __bfloat162float(__float2bfloat16_rn(cw[code * CCH + s * 64 + j]));
            sum += v * v;
        }
        sum += __shfl_xor_sync(~0u, sum, 1);
        sum += __shfl_xor_sync(~0u, sum, 2);
        sum += __shfl_xor_sync(~0u, sum, 4);
        if (s == 0) g_c2[code] = sum;
    }
}

// ---------------- K1: conv(1x1)+BN2+ReLU via mma.sync tf32, bf16 store -----
// Fragment loads via LDS.64: A-frag rows (g, g+8) mapped to adjacent smem
// columns (c0 = mb+16i+2g); B k-pairs adjacent via k_pre permute.
#define ASTR 136
#define BSTR 40
#define ATILE (32 * ASTR)   // 4352 floats = 1088 float4
#define BTILE (128 * BSTR)

__global__ __launch_bounds__(256, 2) void k_conv_mma(
    const float* __restrict__ x,
    const float* __restrict__ bg, const float* __restrict__ bb,
    const float* __restrict__ bm, const float* __restrict__ bv)
{
    extern __shared__ float dsm[];
    float* Abuf[2] = { dsm, dsm + ATILE };
    float* Bbuf[2] = { dsm + 2 * ATILE, dsm + 2 * ATILE + BTILE };
    __shared__ float bnS[128], bnM[128], bnT[128];

    const int tid  = threadIdx.x;
    const int wid  = tid >> 5;
    const int lane = tid & 31;
    const int g    = lane >> 2;
    const int tg   = lane & 3;
    const int warp_m = wid >> 2;
    const int warp_n = wid & 3;

    const int b  = blockIdx.z;
    const int m0 = blockIdx.x * 128;
    const int n0 = blockIdx.y * 128;

    if (tid < 128) {
        int n = n0 + tid;
        bnS[tid] = bg[n] * rsqrtf(bv[n] + EPS);
        bnM[tid] = bm[n];
        bnT[tid] = bb[n];
    }

    const float* xb = x + (size_t)b * CCH * NPIX;

    const int arow = tid >> 3;
    const int mseg = (tid & 7) * 16;
    const int bn   = tid >> 1;
    const int koff = (tid & 1) * 16;

    {
        const float* asrc = xb + (size_t)arow * NPIX + m0 + mseg;
        uint32_t adst = smem_u32(Abuf[0] + arow * ASTR + mseg);
#pragma unroll
        for (int j = 0; j < 4; j++) CP16(adst + j * 16, asrc + j * 4);
        const float* bsrc = g_wr + (size_t)(n0 + bn) * CCH + koff;
        uint32_t bdst = smem_u32(Bbuf[0] + bn * BSTR + koff);
#pragma unroll
        for (int j = 0; j < 4; j++) CP16(bdst + j * 16, bsrc + j * 4);
        CPCOMMIT();
    }

    float c[4][4][4];
#pragma unroll
    for (int i = 0; i < 4; i++)
#pragma unroll
        for (int j = 0; j < 4; j++)
#pragma unroll
            for (int r = 0; r < 4; r++) c[i][j][r] = 0.f;

    for (int kt = 0; kt < 16; kt++) {
        CPWAIT0();
        __syncthreads();

        if (kt < 15) {
            int k0 = (kt + 1) * 32;
            const float* asrc = xb + (size_t)(k0 + arow) * NPIX + m0 + mseg;
            uint32_t adst = smem_u32(Abuf[(kt + 1) & 1] + arow * ASTR + mseg);
#pragma unroll
            for (int j = 0; j < 4; j++) CP16(adst + j * 16, asrc + j * 4);
            const float* bsrc = g_wr + (size_t)(n0 + bn) * CCH + k0 + koff;
            uint32_t bdst = smem_u32(Bbuf[(kt + 1) & 1] + bn * BSTR + koff);
#pragma unroll
            for (int j = 0; j < 4; j++) CP16(bdst + j * 16, bsrc + j * 4);
            CPCOMMIT();
        }

        // in-place tf32 RNA round of A tile, float4-vectorized
        {
            float4* A4 = (float4*)Abuf[kt & 1];
#pragma unroll
            for (int q = 0; q < 4; q++) {
                float4 v = A4[tid + 256 * q];
                v.x = tf32f(v.x); v.y = tf32f(v.y);
                v.z = tf32f(v.z); v.w = tf32f(v.w);
                A4[tid + 256 * q] = v;
            }
            if (tid < 64) {
                float4 v = A4[1024 + tid];
                v.x = tf32f(v.x); v.y = tf32f(v.y);
                v.z = tf32f(v.z); v.w = tf32f(v.w);
                A4[1024 + tid] = v;
            }
        }
        __syncthreads();

        const float* As = Abuf[kt & 1];
        const float* Bs = Bbuf[kt & 1];
        const int mb = warp_m * 64;
        const int nb = warp_n * 32;

#pragma unroll
        for (int s = 0; s < 4; s++) {
            const int kb = s * 8;
            unsigned af[4][4];
#pragma unroll
            for (int i = 0; i < 4; i++) {
                int c0 = mb + i * 16 + 2 * g;
                uint2 va0 = *(const uint2*)&As[(kb + tg) * ASTR + c0];
                uint2 va1 = *(const uint2*)&As[(kb + tg + 4) * ASTR + c0];
                af[i][0] = va0.x;   // frag row g     = pixel c0
                af[i][1] = va0.y;   // frag row g+8   = pixel c0+1
                af[i][2] = va1.x;
                af[i][3] = va1.y;
            }
            unsigned bf[4][2];
#pragma unroll
            for (int j = 0; j < 4; j++) {
                int n = nb + j * 8 + g;
                uint2 vb = *(const uint2*)&Bs[n * BSTR + kb + 2 * tg];
                bf[j][0] = vb.x;    // global k = kb+tg
                bf[j][1] = vb.y;    // global k = kb+tg+4
            }
#pragma unroll
            for (int i = 0; i < 4; i++)
#pragma unroll
                for (int j = 0; j < 4; j++)
                    mma_tf32(c[i][j], af[i], bf[j]);
        }
        __syncthreads();
    }

    // epilogue: frag rows (g,g+8) are pixels (r0, r0+1) after the remap
    const int mb = m0 + warp_m * 64;
    const int nbl = warp_n * 32;
#pragma unroll
    for (int i = 0; i < 4; i++) {
        int r0 = mb + i * 16 + 2 * g;
        __nv_bfloat16* op0 = g_feat + ((size_t)b * NPIX + r0) * CCH + n0;
        __nv_bfloat16* op1 = op0 + (size_t)CCH;     // row r0+1
        float s0 = 0.f, s1 = 0.f;
#pragma unroll
        for (int j = 0; j < 4; j++) {
            int nl = nbl + j * 8 + 2 * tg;
            float sc0 = bnS[nl], sc1 = bnS[nl + 1];
            float u0 = bnM[nl], u1 = bnM[nl + 1];
            float t0 = bnT[nl], t1 = bnT[nl + 1];
            float p00 = fmaxf((c[i][j][0] - u0) * sc0 + t0, 0.f);
            float p01 = fmaxf((c[i][j][1] - u1) * sc1 + t1, 0.f);
            float p10 = fmaxf((c[i][j][2] - u0) * sc0 + t0, 0.f);
            float p11 = fmaxf((c[i][j][3] - u1) * sc1 + t1, 0.f);
            __nv_bfloat162 h0 = __floats2bfloat162_rn(p00, p01);
            __nv_bfloat162 h1 = __floats2bfloat162_rn(p10, p11);
            *(__nv_bfloat162*)(op0 + nl) = h0;
            *(__nv_bfloat162*)(op1 + nl) = h1;
            float q00 = __bfloat162float(h0.x), q01 = __bfloat162float(h0.y);
            float q10 = __bfloat162float(h1.x), q11 = __bfloat162float(h1.y);
            s0 += q00 * q00 + q01 * q01;
            s1 += q10 * q10 + q11 * q11;
        }
        s0 += __shfl_xor_sync(~0u, s0, 1);
        s0 += __shfl_xor_sync(~0u, s0, 2);
        s1 += __shfl_xor_sync(~0u, s1, 1);
        s1 += __shfl_xor_sync(~0u, s1, 2);
        if (tg == 0) {
            atomicAdd(&g_x2[b * NPIX + r0], s0);
            atomicAdd(&g_x2[b * NPIX + r0 + 1], s1);
        }
    }
}

// ---------------- K2: FUSED assign, fully smem-resident feat tile ----------
#define FTW 260     // words per feat row (512 bf16 + 8 pad)
#define AWTW 68     // words per awT row (128 bf16 + 8 pad)
__global__ __launch_bounds__(256) void k_assign(const float* __restrict__ scale)
{
    extern __shared__ unsigned ls[];
    unsigned* ft   = ls;                         // 128 x 260 words (130KB)
    unsigned* awT  = ls + 128 * FTW;             // 32 x 68 words
    float* sc_s = (float*)(awT + 32 * AWTW);     // 32
    float* c2_s = sc_s + 32;                     // 32
    float* x2_s = c2_s + 32;                     // 128

    const int tid  = threadIdx.x;
    const int wid  = tid >> 5;
    const int lane = tid & 31;
    const int g    = lane >> 2;
    const int tg   = lane & 3;
    const int b  = blockIdx.x >> 7;
    const int n0 = (blockIdx.x & 127) * 128;

    const __nv_bfloat16* fbH = g_feat + ((size_t)b * NPIX + n0) * CCH;

    {
        const int row  = tid >> 1;
        const int half = tid & 1;
        uint32_t dbase = smem_u32(ft) + (row * FTW) * 4;
        const __nv_bfloat16* sbase = fbH + (size_t)row * CCH + half * 32;
#pragma unroll
        for (int c = 0; c < 8; c++) {
#pragma unroll
            for (int u = 0; u < 4; u++)
                CP16(dbase + (c * 32 + (half * 4 + u) * 4) * 4, sbase + c * 64 + u * 8);
            CPCOMMIT();
        }
    }

    if (tid < 32) { sc_s[tid] = scale[tid]; c2_s[tid] = g_c2[tid]; }
    if (tid < 128) x2_s[tid] = g_x2[b * NPIX + n0 + tid];

    float c[4][4];
#pragma unroll
    for (int j = 0; j < 4; j++)
#pragma unroll
        for (int r = 0; r < 4; r++) c[j][r] = 0.f;

    const int pb = wid * 16;

#pragma unroll
    for (int ch = 0; ch < 8; ch++) {
        switch (ch) {
            case 0: CPWAITN(7); break; case 1: CPWAITN(6); break;
            case 2: CPWAITN(5); break; case 3: CPWAITN(4); break;
            case 4: CPWAITN(3); break; case 5: CPWAITN(2); break;
            case 6: CPWAITN(1); break; default: CPWAITN(0); break;
        }
        __syncthreads();

#pragma unroll
        for (int ks = 0; ks < 4; ks++) {
            const int ko = ch * 32 + ks * 8;
            unsigned af[4];
            af[0] = ft[(pb + g) * FTW + ko + tg];
            af[1] = ft[(pb + g + 8) * FTW + ko + tg];
            af[2] = ft[(pb + g) * FTW + ko + tg + 4];
            af[3] = ft[(pb + g + 8) * FTW + ko + tg + 4];
#pragma unroll
            for (int j = 0; j < 4; j++) {
                uint2 v = __ldg(&g_cwfH[((ch * 4 + ks) * 4 + j) * 32 + lane]);
                unsigned bf[2] = { v.x, v.y };
                mma_bf16(c[j], af, bf);
            }
        }
    }

    __nv_bfloat16* awTH = (__nv_bfloat16*)awT;
    {
        int r0 = pb + g;
        int r1 = r0 + 8;
        float l0[8], l1[8];
#pragma unroll
        for (int j = 0; j < 4; j++)
#pragma unroll
            for (int h = 0; h < 2; h++) {
                int n = j * 8 + 2 * tg + h;
                l0[j * 2 + h] = sc_s[n] * (x2_s[r0] - 2.f * c[j][h] + c2_s[n]);
                l1[j * 2 + h] = sc_s[n] * (x2_s[r1] - 2.f * c[j][2 + h] + c2_s[n]);
            }
        float m0 = l0[0], m1 = l1[0];
#pragma unroll
        for (int q = 1; q < 8; q++) { m0 = fmaxf(m0, l0[q]); m1 = fmaxf(m1, l1[q]); }
        m0 = fmaxf(m0, __shfl_xor_sync(~0u, m0, 1));
        m0 = fmaxf(m0, __shfl_xor_sync(~0u, m0, 2));
        m1 = fmaxf(m1, __shfl_xor_sync(~0u, m1, 1));
        m1 = fmaxf(m1, __shfl_xor_sync(~0u, m1, 2));
        float s0 = 0.f, s1 = 0.f;
#pragma unroll
        for (int q = 0; q < 8; q++) {
            l0[q] = __expf(l0[q] - m0); s0 += l0[q];
            l1[q] = __expf(l1[q] - m1); s1 += l1[q];
        }
        s0 += __shfl_xor_sync(~0u, s0, 1);
        s0 += __shfl_xor_sync(~0u, s0, 2);
        s1 += __shfl_xor_sync(~0u, s1, 1);
        s1 += __shfl_xor_sync(~0u, s1, 2);
        float r0i = 1.f / s0, r1i = 1.f / s1;
#pragma unroll
        for (int j = 0; j < 4; j++)
#pragma unroll
            for (int h = 0; h < 2; h++) {
                int n = j * 8 + 2 * tg + h;
                awTH[n * (AWTW * 2) + r0] = __float2bfloat16_rn(l0[j * 2 + h] * r0i);
                awTH[n * (AWTW * 2) + r1] = __float2bfloat16_rn(l1[j * 2 + h] * r1i);
            }
    }
    __syncthreads();

    {
        int code = tid >> 3;
        int s = tid & 7;
        float asum = 0.f;
#pragma unroll
        for (int t = 0; t < 16; t++)
            asum += __bfloat162float(awTH[code * (AWTW * 2) + s * 16 + t]);
        asum += __shfl_xor_sync(~0u, asum, 1);
        asum += __shfl_xor_sync(~0u, asum, 2);
        asum += __shfl_xor_sync(~0u, asum, 4);
        if (s == 0) atomicAdd(&g_awsum[b * KCODES + code], asum);
    }

    float e[2][8][4];
#pragma unroll
    for (int i = 0; i < 2; i++)
#pragma unroll
        for (int j = 0; j < 8; j++)
#pragma unroll
            for (int r = 0; r < 4; r++) e[i][j][r] = 0.f;

    const int wc0 = wid * 64;
    const uint32_t ftb = smem_u32(ft);
    const int lrow = lane & 15;

#pragma unroll
    for (int cc = 0; cc < 8; cc++) {
        unsigned af[2][4];
#pragma unroll
        for (int i = 0; i < 2; i++) {
            int code = i * 16 + g;
            af[i][0] = awT[code * AWTW + cc * 8 + tg];
            af[i][1] = awT[(code + 8) * AWTW + cc * 8 + tg];
            af[i][2] = awT[code * AWTW + cc * 8 + tg + 4];
            af[i][3] = awT[(code + 8) * AWTW + cc * 8 + tg + 4];
        }
        uint32_t base = ftb + (cc * 16 + lrow) * (FTW * 4);
#pragma unroll
        for (int j = 0; j < 8; j++) {
            unsigned b0, b1;
            uint32_t addr = base + (wc0 + j * 8) * 2;
            LDMX2T(b0, b1, addr);
            unsigned bf[2] = { b0, b1 };
#pragma unroll
            for (int i = 0; i < 2; i++)
                mma_bf16(e[i][j], af[i], bf);
        }
    }

#pragma unroll
    for (int i = 0; i < 2; i++) {
        int code0 = i * 16 + g;
        float* e0 = g_enc + ((size_t)b * KCODES + code0) * CCH + wc0;
        float* e1 = e0 + (size_t)8 * CCH;
#pragma unroll
        for (int j = 0; j < 8; j++) {
            int nl = j * 8 + 2 * tg;
            atomicAdd(e0 + nl,     e[i][j][0]);
            atomicAdd(e0 + nl + 1, e[i][j][1]);
            atomicAdd(e1 + nl,     e[i][j][2]);
            atomicAdd(e1 + nl + 1, e[i][j][3]);
        }
    }
}

// ---------------- K3: finalize enc -> BN1 + ReLU + mean over codes ----------
__global__ void k_final(const float* __restrict__ cw,
                        const float* __restrict__ g1, const float* __restrict__ b1,
                        const float* __restrict__ m1, const float* __restrict__ v1,
                        float* __restrict__ out)
{
    int b = blockIdx.x;
    int c = threadIdx.x;
    float sum = 0.f;
#pragma unroll
    for (int k = 0; k < KCODES; k++) {
        float cb = __bfloat162float(__float2bfloat16_rn(cw[k * CCH + c]));
        float e = g_enc[(b * KCODES + k) * CCH + c] - g_awsum[b * KCODES + k] * cb;
        float s = g1[k] * rsqrtf(v1[k] + EPS);
        e = (e - m1[k]) * s + b1[k];
        sum += fmaxf(e, 0.f);
    }
    float ef = sum * (1.f / (float)KCODES);
    g_encfeat[b * CCH + c] = ef;
    out[b * CCH + c] = ef;
}

// ---------------- K4: fc + sigmoid -> 1+gamma --------------------------------
__global__ void k_fc(const float* __restrict__ fcw, const float* __restrict__ fcb)
{
    int w = blockIdx.x * 8 + (threadIdx.x >> 5);
    int lane = threadIdx.x & 31;
    int b = w >> 9, co = w & 511;
    const float* wr = fcw + (size_t)co * CCH;
    const float* ef = g_encfeat + b * CCH;
    float s = 0.f;
#pragma unroll
    for (int j = 0; j < 16; j++) s += wr[lane + 32 * j] * ef[lane + 32 * j];
    s += __shfl_xor_sync(~0u, s, 16);
    s += __shfl_xor_sync(~0u, s, 8);
    s += __shfl_xor_sync(~0u, s, 4);
    s += __shfl_xor_sync(~0u, s, 2);
    s += __shfl_xor_sync(~0u, s, 1);
    if (lane == 0)
        g_gamma1p[w] = 1.f + 1.f / (1.f + __expf(-(s + fcb[co])));
}

// ---------------- K5: output = relu(x * (1+gamma)) ---------------------------
__global__ void k_out(const float4* __restrict__ x4, float4* __restrict__ o4, int n4)
{
    int i = blockIdx.x * blockDim.x + threadIdx.x;
    if (i >= n4) return;
    float g = g_gamma1p[i >> 12];
    float4 v = x4[i];
    v.x = fmaxf(v.x * g, 0.f);
    v.y = fmaxf(v.y * g, 0.f);
    v.z = fmaxf(v.z * g, 0.f);
    v.w = fmaxf(v.w * g, 0.f);
    o4[i] = v;
}

// ---------------- launch -----------------------------------------------------
extern "C" void kernel_launch(void* const* d_in, const int* in_sizes, int n_in,
                              void* d_out, int out_size)
{
    const float* x    = (const float*)d_in[0];
    const float* cwn  = (const float*)d_in[1];
    const float* b2g  = (const float*)d_in[2];
    const float* b2b  = (const float*)d_in[3];
    const float* b2m  = (const float*)d_in[4];
    const float* b2v  = (const float*)d_in[5];
    const float* cw   = (const float*)d_in[6];
    const float* sc   = (const float*)d_in[7];
    const float* b1g  = (const float*)d_in[8];
    const float* b1b  = (const float*)d_in[9];
    const float* b1m  = (const float*)d_in[10];
    const float* b1v  = (const float*)d_in[11];
    const float* fcw  = (const float*)d_in[12];
    const float* fcb  = (const float*)d_in[13];
    float* out = (float*)d_out;

    const int conv_smem = (2 * ATILE + 2 * BTILE) * 4;
    cudaFuncSetAttribute(k_conv_mma, cudaFuncAttributeMaxDynamicSharedMemorySize,
                         conv_smem);
    const int assign_smem = (128 * FTW + 32 * AWTW + 32 + 32 + 128) * 4;
    cudaFuncSetAttribute(k_assign, cudaFuncAttributeMaxDynamicSharedMemorySize,
                         assign_smem);

    // launch order keeps k_conv_mma at profiled slot (index 3)
    k_zero<<<(BX * KCODES * CCH + 255) / 256, 256>>>();
    k_pre<<<CCH * CCH / 8 / 256, 256>>>(cwn);
    k_cwprep<<<17, 256>>>(cw);

    dim3 g1(NPIX / 128, CCH / 128, BX);
    k_conv_mma<<<g1, 256, conv_smem>>>(x, b2g, b2b, b2m, b2v);

    k_assign<<<BX * (NPIX / 128), 256, assign_smem>>>(sc);

    k_final<<<BX, CCH>>>(cw, b1g, b1b, b1m, b1v, out);

    k_fc<<<BX * CCH / 8, 256>>>(fcw, fcb);

    int n4 = BX * CCH * NPIX / 4;
    k_out<<<n4 / 256, 256>>>((const float4*)x, (float4*)(out + BX * CCH), n4);
}

// round 16
// speedup vs baseline: 1.3990x; 1.3990x over previous
#include <cuda_runtime.h>
#include <cuda_bf16.h>
#include <cstdint>

#define EPS 1e-5f

#define BX 8
#define CCH 512
#define KCODES 32
#define NPIX 16384   // 128*128

// ---------------- device scratch ----------------
__device__ __nv_bfloat16 g_feat[(size_t)BX * NPIX * CCH];  // bf16 feat, 134MB
__device__ float g_wr[CCH * CCH];                   // tf32-rounded w
__device__ uint2 g_cwfH[4096];                      // bf16 cw B-fragment table
__device__ float g_x2[BX * NPIX];                   // per-pixel |feat|^2 (bf16 vals)
__device__ float g_c2[KCODES];                      // |cw_bf16|^2
__device__ float g_enc[BX * KCODES * CCH];          // [B][K][C]
__device__ float g_awsum[BX * KCODES];              // [B][K]
__device__ float g_encfeat[BX * CCH];               // [B][C]
__device__ float g_gamma1p[BX * CCH];               // 1 + sigmoid(...)

// ---------------- helpers ----------------
__device__ __forceinline__ uint32_t smem_u32(const void* p) {
    uint32_t a;
    asm("{ .reg .u64 t; cvta.to.shared.u64 t, %1; cvt.u32.u64 %0, t; }" : "=r"(a) : "l"(p));
    return a;
}
__device__ __forceinline__ unsigned tf32r(float v) {
    unsigned u; asm("cvt.rna.tf32.f32 %0, %1;" : "=r"(u) : "f"(v)); return u;
}
__device__ __forceinline__ float tf32f(float v) { return __uint_as_float(tf32r(v)); }
#define CP16(dst, src) \
    asm volatile("cp.async.cg.shared.global [%0], [%1], 16;" :: "r"(dst), "l"(src))
#define CPCOMMIT() asm volatile("cp.async.commit_group;" ::: "memory")
#define CPWAIT0()  asm volatile("cp.async.wait_group 0;" ::: "memory")
#define CPWAITN(n) asm volatile("cp.async.wait_group %0;" :: "n"(n) : "memory")

__device__ __forceinline__ void mma_tf32(float* c, const unsigned* a, const unsigned* b) {
    asm volatile("mma.sync.aligned.m16n8k8.row.col.f32.tf32.tf32.f32 "
        "{%0,%1,%2,%3}, {%4,%5,%6,%7}, {%8,%9}, {%0,%1,%2,%3};"
        : "+f"(c[0]), "+f"(c[1]), "+f"(c[2]), "+f"(c[3])
        : "r"(a[0]), "r"(a[1]), "r"(a[2]), "r"(a[3]), "r"(b[0]), "r"(b[1]));
}
__device__ __forceinline__ void mma_bf16(float* c, const unsigned* a, const unsigned* b) {
    asm volatile("mma.sync.aligned.m16n8k16.row.col.f32.bf16.bf16.f32 "
        "{%0,%1,%2,%3}, {%4,%5,%6,%7}, {%8,%9}, {%0,%1,%2,%3};"
        : "+f"(c[0]), "+f"(c[1]), "+f"(c[2]), "+f"(c[3])
        : "r"(a[0]), "r"(a[1]), "r"(a[2]), "r"(a[3]), "r"(b[0]), "r"(b[1]));
}
#define LDMX2T(r0, r1, addr) \
    asm volatile("ldmatrix.sync.aligned.m8n8.x2.trans.shared.b16 {%0,%1}, [%2];" \
        : "=r"(r0), "=r"(r1) : "r"(addr))

__device__ __forceinline__ unsigned bf2pack(float a, float b) {
    __nv_bfloat162 h = __floats2bfloat162_rn(a, b);
    return *(unsigned*)&h;
}

// ---------------- K0: zero accumulators ----------------
__global__ void k_zero() {
    int i = blockIdx.x * 256 + threadIdx.x;
    if (i < BX * KCODES * CCH) g_enc[i] = 0.f;
    if (i < BX * NPIX) g_x2[i] = 0.f;
    if (i < BX * KCODES) g_awsum[i] = 0.f;
}

// ---------------- Kpre: tf32-round w only ----------------
#define NW4 (CCH * CCH / 4)
__global__ void k_pre(const float4* __restrict__ w)
{
    size_t j = (size_t)blockIdx.x * 256 + threadIdx.x;
    if (j < NW4) {
        float4 v = w[j], o;
        o.x = tf32f(v.x); o.y = tf32f(v.y); o.z = tf32f(v.z); o.w = tf32f(v.w);
        ((float4*)g_wr)[j] = o;
    }
}

// ---------------- Kcwprep: merged cw frag table + |cw|^2 ----------------
__global__ void k_cwprep(const float* __restrict__ cw) {
    if (blockIdx.x < 16) {
        int p = blockIdx.x * 256 + threadIdx.x;   // 4096
        int lane = p & 31;
        int j    = (p >> 5) & 3;
        int kk   = p >> 7;
        int code = j * 8 + (lane >> 2);
        int k = kk * 16 + 2 * (lane & 3);
        const float* cr = cw + code * CCH + k;
        uint2 v;
        v.x = bf2pack(cr[0], cr[1]);
        v.y = bf2pack(cr[8], cr[9]);
        g_cwfH[p] = v;
    } else {
        int code = threadIdx.x >> 3;
        int s = threadIdx.x & 7;
        float sum = 0.f;
#pragma unroll
        for (int j = 0; j < 64; j++) {
            float v = __bfloat162float(__float2bfloat16_rn(cw[code * CCH + s * 64 + j]));
            sum += v * v;
        }
        sum += __shfl_xor_sync(~0u, sum, 1);
        sum += __shfl_xor_sync(~0u, sum, 2);
        sum += __shfl_xor_sync(~0u, sum, 4);
        if (s == 0) g_c2[code] = sum;
    }
}

// ---------------- K1: conv(1x1)+BN2+ReLU via mma.sync tf32, bf16 store -----
#define ASTR 136
#define BSTR 40
#define ATILE (32 * ASTR)   // 4352 floats = 1088 float4
#define BTILE (128 * BSTR)

__global__ __launch_bounds__(256, 2) void k_conv_mma(
    const float* __restrict__ x,
    const float* __restrict__ bg, const float* __restrict__ bb,
    const float* __restrict__ bm, const float* __restrict__ bv)
{
    extern __shared__ float dsm[];
    float* Abuf[2] = { dsm, dsm + ATILE };
    float* Bbuf[2] = { dsm + 2 * ATILE, dsm + 2 * ATILE + BTILE };
    __shared__ float bnS[128], bnM[128], bnT[128];

    const int tid  = threadIdx.x;
    const int wid  = tid >> 5;
    const int lane = tid & 31;
    const int g    = lane >> 2;
    const int tg   = lane & 3;
    const int warp_m = wid >> 2;
    const int warp_n = wid & 3;

    const int b  = blockIdx.z;
    const int m0 = blockIdx.x * 128;
    const int n0 = blockIdx.y * 128;

    if (tid < 128) {
        int n = n0 + tid;
        bnS[tid] = bg[n] * rsqrtf(bv[n] + EPS);
        bnM[tid] = bm[n];
        bnT[tid] = bb[n];
    }

    const float* xb = x + (size_t)b * CCH * NPIX;

    const int arow = tid >> 3;
    const int mseg = (tid & 7) * 16;
    const int bn   = tid >> 1;
    const int koff = (tid & 1) * 16;

    {
        const float* asrc = xb + (size_t)arow * NPIX + m0 + mseg;
        uint32_t adst = smem_u32(Abuf[0] + arow * ASTR + mseg);
#pragma unroll
        for (int j = 0; j < 4; j++) CP16(adst + j * 16, asrc + j * 4);
        const float* bsrc = g_wr + (size_t)(n0 + bn) * CCH + koff;
        uint32_t bdst = smem_u32(Bbuf[0] + bn * BSTR + koff);
#pragma unroll
        for (int j = 0; j < 4; j++) CP16(bdst + j * 16, bsrc + j * 4);
        CPCOMMIT();
    }

    float c[4][4][4];
#pragma unroll
    for (int i = 0; i < 4; i++)
#pragma unroll
        for (int j = 0; j < 4; j++)
#pragma unroll
            for (int r = 0; r < 4; r++) c[i][j][r] = 0.f;

    for (int kt = 0; kt < 16; kt++) {
        CPWAIT0();
        __syncthreads();   // cp.async data visible + prior MMAs complete

        if (kt < 15) {
            int k0 = (kt + 1) * 32;
            const float* asrc = xb + (size_t)(k0 + arow) * NPIX + m0 + mseg;
            uint32_t adst = smem_u32(Abuf[(kt + 1) & 1] + arow * ASTR + mseg);
#pragma unroll
            for (int j = 0; j < 4; j++) CP16(adst + j * 16, asrc + j * 4);
            const float* bsrc = g_wr + (size_t)(n0 + bn) * CCH + k0 + koff;
            uint32_t bdst = smem_u32(Bbuf[(kt + 1) & 1] + bn * BSTR + koff);
#pragma unroll
            for (int j = 0; j < 4; j++) CP16(bdst + j * 16, bsrc + j * 4);
            CPCOMMIT();
        }

        // in-place tf32 RNA round of A tile, float4-vectorized (1088 float4)
        {
            float4* A4 = (float4*)Abuf[kt & 1];
#pragma unroll
            for (int q = 0; q < 4; q++) {
                float4 v = A4[tid + 256 * q];
                v.x = tf32f(v.x); v.y = tf32f(v.y);
                v.z = tf32f(v.z); v.w = tf32f(v.w);
                A4[tid + 256 * q] = v;
            }
            if (tid < 64) {
                float4 v = A4[1024 + tid];
                v.x = tf32f(v.x); v.y = tf32f(v.y);
                v.z = tf32f(v.z); v.w = tf32f(v.w);
                A4[1024 + tid] = v;
            }
        }
        __syncthreads();   // cvt complete before fragment reads

        const unsigned* As = (const unsigned*)Abuf[kt & 1];
        const unsigned* Bs = (const unsigned*)Bbuf[kt & 1];
        const int mb = warp_m * 64;
        const int nb = warp_n * 32;

#pragma unroll
        for (int s = 0; s < 4; s++) {
            const int kb = s * 8;
            unsigned af[4][4];
#pragma unroll
            for (int i = 0; i < 4; i++) {
                int m = mb + i * 16 + g;
                af[i][0] = As[(kb + tg) * ASTR + m];
                af[i][1] = As[(kb + tg) * ASTR + m + 8];
                af[i][2] = As[(kb + tg + 4) * ASTR + m];
                af[i][3] = As[(kb + tg + 4) * ASTR + m + 8];
            }
            unsigned bf[4][2];
#pragma unroll
            for (int j = 0; j < 4; j++) {
                int n = nb + j * 8 + g;
                bf[j][0] = Bs[n * BSTR + kb + tg];
                bf[j][1] = Bs[n * BSTR + kb + tg + 4];
            }
#pragma unroll
            for (int i = 0; i < 4; i++)
#pragma unroll
                for (int j = 0; j < 4; j++)
                    mma_tf32(c[i][j], af[i], bf[j]);
        }
        // NOTE: no trailing __syncthreads() — the barrier at the top of the
        // next iteration (after CPWAIT0) already orders these MMA reads of
        // buffer kt&1 before any cp.async writes to it (issued in iter kt+1
        // targeting buffer (kt+2)&1 == kt&1).
    }

    // epilogue: BN + ReLU -> bf16 store + |feat_bf16|^2 partial
    const int mb = m0 + warp_m * 64;
    const int nbl = warp_n * 32;
#pragma unroll
    for (int i = 0; i < 4; i++) {
        int r0 = mb + i * 16 + g;
        __nv_bfloat16* op0 = g_feat + ((size_t)b * NPIX + r0) * CCH + n0;
        __nv_bfloat16* op1 = op0 + (size_t)8 * CCH;
        float s0 = 0.f, s1 = 0.f;
#pragma unroll
        for (int j = 0; j < 4; j++) {
            int nl = nbl + j * 8 + 2 * tg;
            float sc0 = bnS[nl], sc1 = bnS[nl + 1];
            float u0 = bnM[nl], u1 = bnM[nl + 1];
            float t0 = bnT[nl], t1 = bnT[nl + 1];
            float p00 = fmaxf((c[i][j][0] - u0) * sc0 + t0, 0.f);
            float p01 = fmaxf((c[i][j][1] - u1) * sc1 + t1, 0.f);
            float p10 = fmaxf((c[i][j][2] - u0) * sc0 + t0, 0.f);
            float p11 = fmaxf((c[i][j][3] - u1) * sc1 + t1, 0.f);
            __nv_bfloat162 h0 = __floats2bfloat162_rn(p00, p01);
            __nv_bfloat162 h1 = __floats2bfloat162_rn(p10, p11);
            *(__nv_bfloat162*)(op0 + nl) = h0;
            *(__nv_bfloat162*)(op1 + nl) = h1;
            float q00 = __bfloat162float(h0.x), q01 = __bfloat162float(h0.y);
            float q10 = __bfloat162float(h1.x), q11 = __bfloat162float(h1.y);
            s0 += q00 * q00 + q01 * q01;
            s1 += q10 * q10 + q11 * q11;
        }
        s0 += __shfl_xor_sync(~0u, s0, 1);
        s0 += __shfl_xor_sync(~0u, s0, 2);
        s1 += __shfl_xor_sync(~0u, s1, 1);
        s1 += __shfl_xor_sync(~0u, s1, 2);
        if (tg == 0) {
            atomicAdd(&g_x2[b * NPIX + r0], s0);
            atomicAdd(&g_x2[b * NPIX + r0 + 8], s1);
        }
    }
}

// ---------------- K2: FUSED assign, fully smem-resident feat tile ----------
#define FTW 260     // words per feat row (512 bf16 + 8 pad)
#define AWTW 68     // words per awT row (128 bf16 + 8 pad)
__global__ __launch_bounds__(256) void k_assign(const float* __restrict__ scale)
{
    extern __shared__ unsigned ls[];
    unsigned* ft   = ls;                         // 128 x 260 words (130KB)
    unsigned* awT  = ls + 128 * FTW;             // 32 x 68 words
    float* sc_s = (float*)(awT + 32 * AWTW);     // 32
    float* c2_s = sc_s + 32;                     // 32
    float* x2_s = c2_s + 32;                     // 128

    const int tid  = threadIdx.x;
    const int wid  = tid >> 5;
    const int lane = tid & 31;
    const int g    = lane >> 2;
    const int tg   = lane & 3;
    const int b  = blockIdx.x >> 7;
    const int n0 = (blockIdx.x & 127) * 128;

    const __nv_bfloat16* fbH = g_feat + ((size_t)b * NPIX + n0) * CCH;

    {
        const int row  = tid >> 1;
        const int half = tid & 1;
        uint32_t dbase = smem_u32(ft) + (row * FTW) * 4;
        const __nv_bfloat16* sbase = fbH + (size_t)row * CCH + half * 32;
#pragma unroll
        for (int c = 0; c < 8; c++) {
#pragma unroll
            for (int u = 0; u < 4; u++)
                CP16(dbase + (c * 32 + (half * 4 + u) * 4) * 4, sbase + c * 64 + u * 8);
            CPCOMMIT();
        }
    }

    if (tid < 32) { sc_s[tid] = scale[tid]; c2_s[tid] = g_c2[tid]; }
    if (tid < 128) x2_s[tid] = g_x2[b * NPIX + n0 + tid];

    float c[4][4];
#pragma unroll
    for (int j = 0; j < 4; j++)
#pragma unroll
        for (int r = 0; r < 4; r++) c[j][r] = 0.f;

    const int pb = wid * 16;

#pragma unroll
    for (int ch = 0; ch < 8; ch++) {
        switch (ch) {
            case 0: CPWAITN(7); break; case 1: CPWAITN(6); break;
            case 2: CPWAITN(5); break; case 3: CPWAITN(4); break;
            case 4: CPWAITN(3); break; case 5: CPWAITN(2); break;
            case 6: CPWAITN(1); break; default: CPWAITN(0); break;
        }
        __syncthreads();

#pragma unroll
        for (int ks = 0; ks < 4; ks++) {
            const int ko = ch * 32 + ks * 8;
            unsigned af[4];
            af[0] = ft[(pb + g) * FTW + ko + tg];
            af[1] = ft[(pb + g + 8) * FTW + ko + tg];
            af[2] = ft[(pb + g) * FTW + ko + tg + 4];
            af[3] = ft[(pb + g + 8) * FTW + ko + tg + 4];
#pragma unroll
            for (int j = 0; j < 4; j++) {
                uint2 v = __ldg(&g_cwfH[((ch * 4 + ks) * 4 + j) * 32 + lane]);
                unsigned bf[2] = { v.x, v.y };
                mma_bf16(c[j], af, bf);
            }
        }
    }

    __nv_bfloat16* awTH = (__nv_bfloat16*)awT;
    {
        int r0 = pb + g;
        int r1 = r0 + 8;
        float l0[8], l1[8];
#pragma unroll
        for (int j = 0; j < 4; j++)
#pragma unroll
            for (int h = 0; h < 2; h++) {
                int n = j * 8 + 2 * tg + h;
                l0[j * 2 + h] = sc_s[n] * (x2_s[r0] - 2.f * c[j][h] + c2_s[n]);
                l1[j * 2 + h] = sc_s[n] * (x2_s[r1] - 2.f * c[j][2 + h] + c2_s[n]);
            }
        float m0 = l0[0], m1 = l1[0];
#pragma unroll
        for (int q = 1; q < 8; q++) { m0 = fmaxf(m0, l0[q]); m1 = fmaxf(m1, l1[q]); }
        m0 = fmaxf(m0, __shfl_xor_sync(~0u, m0, 1));
        m0 = fmaxf(m0, __shfl_xor_sync(~0u, m0, 2));
        m1 = fmaxf(m1, __shfl_xor_sync(~0u, m1, 1));
        m1 = fmaxf(m1, __shfl_xor_sync(~0u, m1, 2));
        float s0 = 0.f, s1 = 0.f;
#pragma unroll
        for (int q = 0; q < 8; q++) {
            l0[q] = __expf(l0[q] - m0); s0 += l0[q];
            l1[q] = __expf(l1[q] - m1); s1 += l1[q];
        }
        s0 += __shfl_xor_sync(~0u, s0, 1);
        s0 += __shfl_xor_sync(~0u, s0, 2);
        s1 += __shfl_xor_sync(~0u, s1, 1);
        s1 += __shfl_xor_sync(~0u, s1, 2);
        float r0i = 1.f / s0, r1i = 1.f / s1;
#pragma unroll
        for (int j = 0; j < 4; j++)
#pragma unroll
            for (int h = 0; h < 2; h++) {
                int n = j * 8 + 2 * tg + h;
                awTH[n * (AWTW * 2) + r0] = __float2bfloat16_rn(l0[j * 2 + h] * r0i);
                awTH[n * (AWTW * 2) + r1] = __float2bfloat16_rn(l1[j * 2 + h] * r1i);
            }
    }
    __syncthreads();

    {
        int code = tid >> 3;
        int s = tid & 7;
        float asum = 0.f;
#pragma unroll
        for (int t = 0; t < 16; t++)
            asum += __bfloat162float(awTH[code * (AWTW * 2) + s * 16 + t]);
        asum += __shfl_xor_sync(~0u, asum, 1);
        asum += __shfl_xor_sync(~0u, asum, 2);
        asum += __shfl_xor_sync(~0u, asum, 4);
        if (s == 0) atomicAdd(&g_awsum[b * KCODES + code], asum);
    }

    float e[2][8][4];
#pragma unroll
    for (int i = 0; i < 2; i++)
#pragma unroll
        for (int j = 0; j < 8; j++)
#pragma unroll
            for (int r = 0; r < 4; r++) e[i][j][r] = 0.f;

    const int wc0 = wid * 64;
    const uint32_t ftb = smem_u32(ft);
    const int lrow = lane & 15;

#pragma unroll
    for (int cc = 0; cc < 8; cc++) {
        unsigned af[2][4];
#pragma unroll
        for (int i = 0; i < 2; i++) {
            int code = i * 16 + g;
            af[i][0] = awT[code * AWTW + cc * 8 + tg];
            af[i][1] = awT[(code + 8) * AWTW + cc * 8 + tg];
            af[i][2] = awT[code * AWTW + cc * 8 + tg + 4];
            af[i][3] = awT[(code + 8) * AWTW + cc * 8 + tg + 4];
        }
        uint32_t base = ftb + (cc * 16 + lrow) * (FTW * 4);
#pragma unroll
        for (int j = 0; j < 8; j++) {
            unsigned b0, b1;
            uint32_t addr = base + (wc0 + j * 8) * 2;
            LDMX2T(b0, b1, addr);
            unsigned bf[2] = { b0, b1 };
#pragma unroll
            for (int i = 0; i < 2; i++)
                mma_bf16(e[i][j], af[i], bf);
        }
    }

#pragma unroll
    for (int i = 0; i < 2; i++) {
        int code0 = i * 16 + g;
        float* e0 = g_enc + ((size_t)b * KCODES + code0) * CCH + wc0;
        float* e1 = e0 + (size_t)8 * CCH;
#pragma unroll
        for (int j = 0; j < 8; j++) {
            int nl = j * 8 + 2 * tg;
            atomicAdd(e0 + nl,     e[i][j][0]);
            atomicAdd(e0 + nl + 1, e[i][j][1]);
            atomicAdd(e1 + nl,     e[i][j][2]);
            atomicAdd(e1 + nl + 1, e[i][j][3]);
        }
    }
}

// ---------------- K3: finalize enc -> BN1 + ReLU + mean over codes ----------
__global__ void k_final(const float* __restrict__ cw,
                        const float* __restrict__ g1, const float* __restrict__ b1,
                        const float* __restrict__ m1, const float* __restrict__ v1,
                        float* __restrict__ out)
{
    int b = blockIdx.x;
    int c = threadIdx.x;
    float sum = 0.f;
#pragma unroll
    for (int k = 0; k < KCODES; k++) {
        float cb = __bfloat162float(__float2bfloat16_rn(cw[k * CCH + c]));
        float e = g_enc[(b * KCODES + k) * CCH + c] - g_awsum[b * KCODES + k] * cb;
        float s = g1[k] * rsqrtf(v1[k] + EPS);
        e = (e - m1[k]) * s + b1[k];
        sum += fmaxf(e, 0.f);
    }
    float ef = sum * (1.f / (float)KCODES);
    g_encfeat[b * CCH + c] = ef;
    out[b * CCH + c] = ef;
}

// ---------------- K4: fc + sigmoid -> 1+gamma --------------------------------
__global__ void k_fc(const float* __restrict__ fcw, const float* __restrict__ fcb)
{
    int w = blockIdx.x * 8 + (threadIdx.x >> 5);
    int lane = threadIdx.x & 31;
    int b = w >> 9, co = w & 511;
    const float* wr = fcw + (size_t)co * CCH;
    const float* ef = g_encfeat + b * CCH;
    float s = 0.f;
#pragma unroll
    for (int j = 0; j < 16; j++) s += wr[lane + 32 * j] * ef[lane + 32 * j];
    s += __shfl_xor_sync(~0u, s, 16);
    s += __shfl_xor_sync(~0u, s, 8);
    s += __shfl_xor_sync(~0u, s, 4);
    s += __shfl_xor_sync(~0u, s, 2);
    s += __shfl_xor_sync(~0u, s, 1);
    if (lane == 0)
        g_gamma1p[w] = 1.f + 1.f / (1.f + __expf(-(s + fcb[co])));
}

// ---------------- K5: output = relu(x * (1+gamma)) ---------------------------
__global__ void k_out(const float4* __restrict__ x4, float4* __restrict__ o4, int n4)
{
    int i = blockIdx.x * blockDim.x + threadIdx.x;
    if (i >= n4) return;
    float g = g_gamma1p[i >> 12];
    float4 v = x4[i];
    v.x = fmaxf(v.x * g, 0.f);
    v.y = fmaxf(v.y * g, 0.f);
    v.z = fmaxf(v.z * g, 0.f);
    v.w = fmaxf(v.w * g, 0.f);
    o4[i] = v;
}

// ---------------- launch -----------------------------------------------------
extern "C" void kernel_launch(void* const* d_in, const int* in_sizes, int n_in,
                              void* d_out, int out_size)
{
    const float* x    = (const float*)d_in[0];
    const float* cwn  = (const float*)d_in[1];
    const float* b2g  = (const float*)d_in[2];
    const float* b2b  = (const float*)d_in[3];
    const float* b2m  = (const float*)d_in[4];
    const float* b2v  = (const float*)d_in[5];
    const float* cw   = (const float*)d_in[6];
    const float* sc   = (const float*)d_in[7];
    const float* b1g  = (const float*)d_in[8];
    const float* b1b  = (const float*)d_in[9];
    const float* b1m  = (const float*)d_in[10];
    const float* b1v  = (const float*)d_in[11];
    const float* fcw  = (const float*)d_in[12];
    const float* fcb  = (const float*)d_in[13];
    float* out = (float*)d_out;

    const int conv_smem = (2 * ATILE + 2 * BTILE) * 4;
    cudaFuncSetAttribute(k_conv_mma, cudaFuncAttributeMaxDynamicSharedMemorySize,
                         conv_smem);
    const int assign_smem = (128 * FTW + 32 * AWTW + 32 + 32 + 128) * 4;
    cudaFuncSetAttribute(k_assign, cudaFuncAttributeMaxDynamicSharedMemorySize,
                         assign_smem);

    // launch order keeps k_conv_mma at profiled slot (index 3)
    k_zero<<<(BX * KCODES * CCH + 255) / 256, 256>>>();
    k_pre<<<(NW4 + 255) / 256, 256>>>((const float4*)cwn);
    k_cwprep<<<17, 256>>>(cw);

    dim3 g1(NPIX / 128, CCH / 128, BX);
    k_conv_mma<<<g1, 256, conv_smem>>>(x, b2g, b2b, b2m, b2v);

    k_assign<<<BX * (NPIX / 128), 256, assign_smem>>>(sc);

    k_final<<<BX, CCH>>>(cw, b1g, b1b, b1m, b1v, out);

    k_fc<<<BX * CCH / 8, 256>>>(fcw, fcb);

    int n4 = BX * CCH * NPIX / 4;
    k_out<<<n4 / 256, 256>>>((const float4*)x, (float4*)(out + BX * CCH), n4);
}

// round 17
// speedup vs baseline: 1.6821x; 1.2023x over previous
#include <cuda_runtime.h>
#include <cuda_bf16.h>
#include <cstdint>

#define EPS 1e-5f

#define BX 8
#define CCH 512
#define KCODES 32
#define NPIX 16384   // 128*128

// ---------------- device scratch ----------------
__device__ __nv_bfloat16 g_feat[(size_t)BX * NPIX * CCH];  // bf16 feat, 134MB
__device__ float g_wr[CCH * CCH];                   // tf32-rounded w
__device__ uint2 g_cwfH[4096];                      // bf16 cw B-fragment table
__device__ float g_x2[BX * NPIX];                   // per-pixel |feat|^2 (bf16 vals)
__device__ float g_c2[KCODES];                      // |cw_bf16|^2
__device__ float g_enc[BX * KCODES * CCH];          // [B][K][C]
__device__ float g_awsum[BX * KCODES];              // [B][K]
__device__ float g_encfeat[BX * CCH];               // [B][C]
__device__ float g_gamma1p[BX * CCH];               // 1 + sigmoid(...)

// ---------------- helpers ----------------
__device__ __forceinline__ uint32_t smem_u32(const void* p) {
    uint32_t a;
    asm("{ .reg .u64 t; cvta.to.shared.u64 t, %1; cvt.u32.u64 %0, t; }" : "=r"(a) : "l"(p));
    return a;
}
__device__ __forceinline__ unsigned tf32r(float v) {
    unsigned u; asm("cvt.rna.tf32.f32 %0, %1;" : "=r"(u) : "f"(v)); return u;
}
__device__ __forceinline__ float tf32f(float v) { return __uint_as_float(tf32r(v)); }
#define CP16(dst, src) \
    asm volatile("cp.async.cg.shared.global [%0], [%1], 16;" :: "r"(dst), "l"(src))
#define CPCOMMIT() asm volatile("cp.async.commit_group;" ::: "memory")
#define CPWAIT0()  asm volatile("cp.async.wait_group 0;" ::: "memory")
#define CPWAITN(n) asm volatile("cp.async.wait_group %0;" :: "n"(n) : "memory")

__device__ __forceinline__ void mma_tf32(float* c, const unsigned* a, const unsigned* b) {
    asm volatile("mma.sync.aligned.m16n8k8.row.col.f32.tf32.tf32.f32 "
        "{%0,%1,%2,%3}, {%4,%5,%6,%7}, {%8,%9}, {%0,%1,%2,%3};"
        : "+f"(c[0]), "+f"(c[1]), "+f"(c[2]), "+f"(c[3])
        : "r"(a[0]), "r"(a[1]), "r"(a[2]), "r"(a[3]), "r"(b[0]), "r"(b[1]));
}
__device__ __forceinline__ void mma_bf16(float* c, const unsigned* a, const unsigned* b) {
    asm volatile("mma.sync.aligned.m16n8k16.row.col.f32.bf16.bf16.f32 "
        "{%0,%1,%2,%3}, {%4,%5,%6,%7}, {%8,%9}, {%0,%1,%2,%3};"
        : "+f"(c[0]), "+f"(c[1]), "+f"(c[2]), "+f"(c[3])
        : "r"(a[0]), "r"(a[1]), "r"(a[2]), "r"(a[3]), "r"(b[0]), "r"(b[1]));
}
#define LDMX2T(r0, r1, addr) \
    asm volatile("ldmatrix.sync.aligned.m8n8.x2.trans.shared.b16 {%0,%1}, [%2];" \
        : "=r"(r0), "=r"(r1) : "r"(addr))

__device__ __forceinline__ unsigned bf2pack(float a, float b) {
    __nv_bfloat162 h = __floats2bfloat162_rn(a, b);
    return *(unsigned*)&h;
}

// ---------------- K0: zero accumulators ----------------
__global__ void k_zero() {
    int i = blockIdx.x * 256 + threadIdx.x;
    if (i < BX * KCODES * CCH) g_enc[i] = 0.f;
    if (i < BX * NPIX) g_x2[i] = 0.f;
    if (i < BX * KCODES) g_awsum[i] = 0.f;
}

// ---------------- Kpre: tf32-round w only ----------------
#define NW4 (CCH * CCH / 4)
__global__ void k_pre(const float4* __restrict__ w)
{
    size_t j = (size_t)blockIdx.x * 256 + threadIdx.x;
    if (j < NW4) {
        float4 v = w[j], o;
        o.x = tf32f(v.x); o.y = tf32f(v.y); o.z = tf32f(v.z); o.w = tf32f(v.w);
        ((float4*)g_wr)[j] = o;
    }
}

// ---------------- Kcwprep: merged cw frag table + |cw|^2 ----------------
__global__ void k_cwprep(const float* __restrict__ cw) {
    if (blockIdx.x < 16) {
        int p = blockIdx.x * 256 + threadIdx.x;   // 4096
        int lane = p & 31;
        int j    = (p >> 5) & 3;
        int kk   = p >> 7;
        int code = j * 8 + (lane >> 2);
        int k = kk * 16 + 2 * (lane & 3);
        const float* cr = cw + code * CCH + k;
        uint2 v;
        v.x = bf2pack(cr[0], cr[1]);
        v.y = bf2pack(cr[8], cr[9]);
        g_cwfH[p] = v;
    } else {
        int code = threadIdx.x >> 3;
        int s = threadIdx.x & 7;
        float sum = 0.f;
#pragma unroll
        for (int j = 0; j < 64; j++) {
            float v = __bfloat162float(__float2bfloat16_rn(cw[code * CCH + s * 64 + j]));
            sum += v * v;
        }
        sum += __shfl_xor_sync(~0u, sum, 1);
        sum += __shfl_xor_sync(~0u, sum, 2);
        sum += __shfl_xor_sync(~0u, sum, 4);
        if (s == 0) g_c2[code] = sum;
    }
}

// ---------------- K1: conv(1x1)+BN2+ReLU via mma.sync tf32, bf16 store -----
// Loader mappings chosen so LDGSTS store-side is 4-wavefront (conflict-free):
//  A: row = 4*(tid>>5)+(tid&3), col4 = ((tid&31)>>2)+8u  -> groups (2a+c8)&7 all-8
//  B: n = 16*(tid>>5)+(lane&15), col4 = (lane>>4)+2u     -> groups (2m+c+2u)&7 all-8
#define ASTR 136
#define BSTR 40
#define ATILE (32 * ASTR)   // 4352 floats = 1088 float4
#define BTILE (128 * BSTR)

__global__ __launch_bounds__(256, 2) void k_conv_mma(
    const float* __restrict__ x,
    const float* __restrict__ bg, const float* __restrict__ bb,
    const float* __restrict__ bm, const float* __restrict__ bv)
{
    extern __shared__ float dsm[];
    float* Abuf[2] = { dsm, dsm + ATILE };
    float* Bbuf[2] = { dsm + 2 * ATILE, dsm + 2 * ATILE + BTILE };
    __shared__ float bnS[128], bnM[128], bnT[128];

    const int tid  = threadIdx.x;
    const int wid  = tid >> 5;
    const int lane = tid & 31;
    const int g    = lane >> 2;
    const int tg   = lane & 3;
    const int warp_m = wid >> 2;
    const int warp_n = wid & 3;

    const int b  = blockIdx.z;
    const int m0 = blockIdx.x * 128;
    const int n0 = blockIdx.y * 128;

    if (tid < 128) {
        int n = n0 + tid;
        bnS[tid] = bg[n] * rsqrtf(bv[n] + EPS);
        bnM[tid] = bm[n];
        bnT[tid] = bb[n];
    }

    const float* xb = x + (size_t)b * CCH * NPIX;

    // conflict-free loader indices
    const int arow = (tid >> 5) * 4 + (tid & 3);    // k-row 0..31
    const int ac8  = (tid & 31) >> 2;               // 0..7
    const int brow = (tid >> 5) * 16 + (lane & 15); // n-row 0..127
    const int bc   = lane >> 4;                     // 0..1

    {
        const float* asrc = xb + (size_t)arow * NPIX + m0;
        uint32_t adst = smem_u32(Abuf[0] + arow * ASTR);
#pragma unroll
        for (int u = 0; u < 4; u++) {
            int col4 = ac8 + 8 * u;
            CP16(adst + col4 * 16, asrc + col4 * 4);
        }
        const float* bsrc = g_wr + (size_t)(n0 + brow) * CCH;
        uint32_t bdst = smem_u32(Bbuf[0] + brow * BSTR);
#pragma unroll
        for (int u = 0; u < 4; u++) {
            int col4 = bc + 2 * u;
            CP16(bdst + col4 * 16, bsrc + col4 * 4);
        }
        CPCOMMIT();
    }

    float c[4][4][4];
#pragma unroll
    for (int i = 0; i < 4; i++)
#pragma unroll
        for (int j = 0; j < 4; j++)
#pragma unroll
            for (int r = 0; r < 4; r++) c[i][j][r] = 0.f;

    for (int kt = 0; kt < 16; kt++) {
        CPWAIT0();
        __syncthreads();   // cp.async data visible + prior MMAs complete

        if (kt < 15) {
            int k0 = (kt + 1) * 32;
            const float* asrc = xb + (size_t)(k0 + arow) * NPIX + m0;
            uint32_t adst = smem_u32(Abuf[(kt + 1) & 1] + arow * ASTR);
#pragma unroll
            for (int u = 0; u < 4; u++) {
                int col4 = ac8 + 8 * u;
                CP16(adst + col4 * 16, asrc + col4 * 4);
            }
            const float* bsrc = g_wr + (size_t)(n0 + brow) * CCH + k0;
            uint32_t bdst = smem_u32(Bbuf[(kt + 1) & 1] + brow * BSTR);
#pragma unroll
            for (int u = 0; u < 4; u++) {
                int col4 = bc + 2 * u;
                CP16(bdst + col4 * 16, bsrc + col4 * 4);
            }
            CPCOMMIT();
        }

        // in-place tf32 RNA round of A tile, float4-vectorized (1088 float4)
        {
            float4* A4 = (float4*)Abuf[kt & 1];
#pragma unroll
            for (int q = 0; q < 4; q++) {
                float4 v = A4[tid + 256 * q];
                v.x = tf32f(v.x); v.y = tf32f(v.y);
                v.z = tf32f(v.z); v.w = tf32f(v.w);
                A4[tid + 256 * q] = v;
            }
            if (tid < 64) {
                float4 v = A4[1024 + tid];
                v.x = tf32f(v.x); v.y = tf32f(v.y);
                v.z = tf32f(v.z); v.w = tf32f(v.w);
                A4[1024 + tid] = v;
            }
        }
        __syncthreads();   // cvt complete before fragment reads

        const unsigned* As = (const unsigned*)Abuf[kt & 1];
        const unsigned* Bs = (const unsigned*)Bbuf[kt & 1];
        const int mb = warp_m * 64;
        const int nb = warp_n * 32;

#pragma unroll
        for (int s = 0; s < 4; s++) {
            const int kb = s * 8;
            unsigned af[4][4];
#pragma unroll
            for (int i = 0; i < 4; i++) {
                int m = mb + i * 16 + g;
                af[i][0] = As[(kb + tg) * ASTR + m];
                af[i][1] = As[(kb + tg) * ASTR + m + 8];
                af[i][2] = As[(kb + tg + 4) * ASTR + m];
                af[i][3] = As[(kb + tg + 4) * ASTR + m + 8];
            }
            unsigned bf[4][2];
#pragma unroll
            for (int j = 0; j < 4; j++) {
                int n = nb + j * 8 + g;
                bf[j][0] = Bs[n * BSTR + kb + tg];
                bf[j][1] = Bs[n * BSTR + kb + tg + 4];
            }
#pragma unroll
            for (int i = 0; i < 4; i++)
#pragma unroll
                for (int j = 0; j < 4; j++)
                    mma_tf32(c[i][j], af[i], bf[j]);
        }
        // no trailing barrier: next iteration's top barrier provides ordering
    }

    // epilogue: BN + ReLU -> bf16 store + |feat_bf16|^2 partial
    const int mb = m0 + warp_m * 64;
    const int nbl = warp_n * 32;
#pragma unroll
    for (int i = 0; i < 4; i++) {
        int r0 = mb + i * 16 + g;
        __nv_bfloat16* op0 = g_feat + ((size_t)b * NPIX + r0) * CCH + n0;
        __nv_bfloat16* op1 = op0 + (size_t)8 * CCH;
        float s0 = 0.f, s1 = 0.f;
#pragma unroll
        for (int j = 0; j < 4; j++) {
            int nl = nbl + j * 8 + 2 * tg;
            float sc0 = bnS[nl], sc1 = bnS[nl + 1];
            float u0 = bnM[nl], u1 = bnM[nl + 1];
            float t0 = bnT[nl], t1 = bnT[nl + 1];
            float p00 = fmaxf((c[i][j][0] - u0) * sc0 + t0, 0.f);
            float p01 = fmaxf((c[i][j][1] - u1) * sc1 + t1, 0.f);
            float p10 = fmaxf((c[i][j][2] - u0) * sc0 + t0, 0.f);
            float p11 = fmaxf((c[i][j][3] - u1) * sc1 + t1, 0.f);
            __nv_bfloat162 h0 = __floats2bfloat162_rn(p00, p01);
            __nv_bfloat162 h1 = __floats2bfloat162_rn(p10, p11);
            *(__nv_bfloat162*)(op0 + nl) = h0;
            *(__nv_bfloat162*)(op1 + nl) = h1;
            float q00 = __bfloat162float(h0.x), q01 = __bfloat162float(h0.y);
            float q10 = __bfloat162float(h1.x), q11 = __bfloat162float(h1.y);
            s0 += q00 * q00 + q01 * q01;
            s1 += q10 * q10 + q11 * q11;
        }
        s0 += __shfl_xor_sync(~0u, s0, 1);
        s0 += __shfl_xor_sync(~0u, s0, 2);
        s1 += __shfl_xor_sync(~0u, s1, 1);
        s1 += __shfl_xor_sync(~0u, s1, 2);
        if (tg == 0) {
            atomicAdd(&g_x2[b * NPIX + r0], s0);
            atomicAdd(&g_x2[b * NPIX + r0 + 8], s1);
        }
    }
}

// ---------------- K2: FUSED assign, fully smem-resident feat tile ----------
#define FTW 260     // words per feat row (512 bf16 + 8 pad)
#define AWTW 68     // words per awT row (128 bf16 + 8 pad)
__global__ __launch_bounds__(256) void k_assign(const float* __restrict__ scale)
{
    extern __shared__ unsigned ls[];
    unsigned* ft   = ls;                         // 128 x 260 words (130KB)
    unsigned* awT  = ls + 128 * FTW;             // 32 x 68 words
    float* sc_s = (float*)(awT + 32 * AWTW);     // 32
    float* c2_s = sc_s + 32;                     // 32
    float* x2_s = c2_s + 32;                     // 128

    const int tid  = threadIdx.x;
    const int wid  = tid >> 5;
    const int lane = tid & 31;
    const int g    = lane >> 2;
    const int tg   = lane & 3;
    const int b  = blockIdx.x >> 7;
    const int n0 = (blockIdx.x & 127) * 128;

    const __nv_bfloat16* fbH = g_feat + ((size_t)b * NPIX + n0) * CCH;

    {
        const int row  = tid >> 1;
        const int half = tid & 1;
        uint32_t dbase = smem_u32(ft) + (row * FTW) * 4;
        const __nv_bfloat16* sbase = fbH + (size_t)row * CCH + half * 32;
#pragma unroll
        for (int c = 0; c < 8; c++) {
#pragma unroll
            for (int u = 0; u < 4; u++)
                CP16(dbase + (c * 32 + (half * 4 + u) * 4) * 4, sbase + c * 64 + u * 8);
            CPCOMMIT();
        }
    }

    if (tid < 32) { sc_s[tid] = scale[tid]; c2_s[tid] = g_c2[tid]; }
    if (tid < 128) x2_s[tid] = g_x2[b * NPIX + n0 + tid];

    float c[4][4];
#pragma unroll
    for (int j = 0; j < 4; j++)
#pragma unroll
        for (int r = 0; r < 4; r++) c[j][r] = 0.f;

    const int pb = wid * 16;

#pragma unroll
    for (int ch = 0; ch < 8; ch++) {
        switch (ch) {
            case 0: CPWAITN(7); break; case 1: CPWAITN(6); break;
            case 2: CPWAITN(5); break; case 3: CPWAITN(4); break;
            case 4: CPWAITN(3); break; case 5: CPWAITN(2); break;
            case 6: CPWAITN(1); break; default: CPWAITN(0); break;
        }
        __syncthreads();

#pragma unroll
        for (int ks = 0; ks < 4; ks++) {
            const int ko = ch * 32 + ks * 8;
            unsigned af[4];
            af[0] = ft[(pb + g) * FTW + ko + tg];
            af[1] = ft[(pb + g + 8) * FTW + ko + tg];
            af[2] = ft[(pb + g) * FTW + ko + tg + 4];
            af[3] = ft[(pb + g + 8) * FTW + ko + tg + 4];
#pragma unroll
            for (int j = 0; j < 4; j++) {
                uint2 v = __ldg(&g_cwfH[((ch * 4 + ks) * 4 + j) * 32 + lane]);
                unsigned bf[2] = { v.x, v.y };
                mma_bf16(c[j], af, bf);
            }
        }
    }

    __nv_bfloat16* awTH = (__nv_bfloat16*)awT;
    {
        int r0 = pb + g;
        int r1 = r0 + 8;
        float l0[8], l1[8];
#pragma unroll
        for (int j = 0; j < 4; j++)
#pragma unroll
            for (int h = 0; h < 2; h++) {
                int n = j * 8 + 2 * tg + h;
                l0[j * 2 + h] = sc_s[n] * (x2_s[r0] - 2.f * c[j][h] + c2_s[n]);
                l1[j * 2 + h] = sc_s[n] * (x2_s[r1] - 2.f * c[j][2 + h] + c2_s[n]);
            }
        float m0 = l0[0], m1 = l1[0];
#pragma unroll
        for (int q = 1; q < 8; q++) { m0 = fmaxf(m0, l0[q]); m1 = fmaxf(m1, l1[q]); }
        m0 = fmaxf(m0, __shfl_xor_sync(~0u, m0, 1));
        m0 = fmaxf(m0, __shfl_xor_sync(~0u, m0, 2));
        m1 = fmaxf(m1, __shfl_xor_sync(~0u, m1, 1));
        m1 = fmaxf(m1, __shfl_xor_sync(~0u, m1, 2));
        float s0 = 0.f, s1 = 0.f;
#pragma unroll
        for (int q = 0; q < 8; q++) {
            l0[q] = __expf(l0[q] - m0); s0 += l0[q];
            l1[q] = __expf(l1[q] - m1); s1 += l1[q];
        }
        s0 += __shfl_xor_sync(~0u, s0, 1);
        s0 += __shfl_xor_sync(~0u, s0, 2);
        s1 += __shfl_xor_sync(~0u, s1, 1);
        s1 += __shfl_xor_sync(~0u, s1, 2);
        float r0i = 1.f / s0, r1i = 1.f / s1;
#pragma unroll
        for (int j = 0; j < 4; j++)
#pragma unroll
            for (int h = 0; h < 2; h++) {
                int n = j * 8 + 2 * tg + h;
                awTH[n * (AWTW * 2) + r0] = __float2bfloat16_rn(l0[j * 2 + h] * r0i);
                awTH[n * (AWTW * 2) + r1] = __float2bfloat16_rn(l1[j * 2 + h] * r1i);
            }
    }
    __syncthreads();

    {
        int code = tid >> 3;
        int s = tid & 7;
        float asum = 0.f;
#pragma unroll
        for (int t = 0; t < 16; t++)
            asum += __bfloat162float(awTH[code * (AWTW * 2) + s * 16 + t]);
        asum += __shfl_xor_sync(~0u, asum, 1);
        asum += __shfl_xor_sync(~0u, asum, 2);
        asum += __shfl_xor_sync(~0u, asum, 4);
        if (s == 0) atomicAdd(&g_awsum[b * KCODES + code], asum);
    }

    float e[2][8][4];
#pragma unroll
    for (int i = 0; i < 2; i++)
#pragma unroll
        for (int j = 0; j < 8; j++)
#pragma unroll
            for (int r = 0; r < 4; r++) e[i][j][r] = 0.f;

    const int wc0 = wid * 64;
    const uint32_t ftb = smem_u32(ft);
    const int lrow = lane & 15;

#pragma unroll
    for (int cc = 0; cc < 8; cc++) {
        unsigned af[2][4];
#pragma unroll
        for (int i = 0; i < 2; i++) {
            int code = i * 16 + g;
            af[i][0] = awT[code * AWTW + cc * 8 + tg];
            af[i][1] = awT[(code + 8) * AWTW + cc * 8 + tg];
            af[i][2] = awT[code * AWTW + cc * 8 + tg + 4];
            af[i][3] = awT[(code + 8) * AWTW + cc * 8 + tg + 4];
        }
        uint32_t base = ftb + (cc * 16 + lrow) * (FTW * 4);
#pragma unroll
        for (int j = 0; j < 8; j++) {
            unsigned b0, b1;
            uint32_t addr = base + (wc0 + j * 8) * 2;
            LDMX2T(b0, b1, addr);
            unsigned bf[2] = { b0, b1 };
#pragma unroll
            for (int i = 0; i < 2; i++)
                mma_bf16(e[i][j], af[i], bf);
        }
    }

#pragma unroll
    for (int i = 0; i < 2; i++) {
        int code0 = i * 16 + g;
        float* e0 = g_enc + ((size_t)b * KCODES + code0) * CCH + wc0;
        float* e1 = e0 + (size_t)8 * CCH;
#pragma unroll
        for (int j = 0; j < 8; j++) {
            int nl = j * 8 + 2 * tg;
            atomicAdd(e0 + nl,     e[i][j][0]);
            atomicAdd(e0 + nl + 1, e[i][j][1]);
            atomicAdd(e1 + nl,     e[i][j][2]);
            atomicAdd(e1 + nl + 1, e[i][j][3]);
        }
    }
}

// ---------------- K3: finalize enc -> BN1 + ReLU + mean over codes ----------
__global__ void k_final(const float* __restrict__ cw,
                        const float* __restrict__ g1, const float* __restrict__ b1,
                        const float* __restrict__ m1, const float* __restrict__ v1,
                        float* __restrict__ out)
{
    int b = blockIdx.x;
    int c = threadIdx.x;
    float sum = 0.f;
#pragma unroll
    for (int k = 0; k < KCODES; k++) {
        float cb = __bfloat162float(__float2bfloat16_rn(cw[k * CCH + c]));
        float e = g_enc[(b * KCODES + k) * CCH + c] - g_awsum[b * KCODES + k] * cb;
        float s = g1[k] * rsqrtf(v1[k] + EPS);
        e = (e - m1[k]) * s + b1[k];
        sum += fmaxf(e, 0.f);
    }
    float ef = sum * (1.f / (float)KCODES);
    g_encfeat[b * CCH + c] = ef;
    out[b * CCH + c] = ef;
}

// ---------------- K4: fc + sigmoid -> 1+gamma --------------------------------
__global__ void k_fc(const float* __restrict__ fcw, const float* __restrict__ fcb)
{
    int w = blockIdx.x * 8 + (threadIdx.x >> 5);
    int lane = threadIdx.x & 31;
    int b = w >> 9, co = w & 511;
    const float* wr = fcw + (size_t)co * CCH;
    const float* ef = g_encfeat + b * CCH;
    float s = 0.f;
#pragma unroll
    for (int j = 0; j < 16; j++) s += wr[lane + 32 * j] * ef[lane + 32 * j];
    s += __shfl_xor_sync(~0u, s, 16);
    s += __shfl_xor_sync(~0u, s, 8);
    s += __shfl_xor_sync(~0u, s, 4);
    s += __shfl_xor_sync(~0u, s, 2);
    s += __shfl_xor_sync(~0u, s, 1);
    if (lane == 0)
        g_gamma1p[w] = 1.f + 1.f / (1.f + __expf(-(s + fcb[co])));
}

// ---------------- K5: output = relu(x * (1+gamma)) ---------------------------
__global__ void k_out(const float4* __restrict__ x4, float4* __restrict__ o4, int n4)
{
    int i = blockIdx.x * blockDim.x + threadIdx.x;
    if (i >= n4) return;
    float g = g_gamma1p[i >> 12];
    float4 v = x4[i];
    v.x = fmaxf(v.x * g, 0.f);
    v.y = fmaxf(v.y * g, 0.f);
    v.z = fmaxf(v.z * g, 0.f);
    v.w = fmaxf(v.w * g, 0.f);
    o4[i] = v;
}

// ---------------- launch -----------------------------------------------------
extern "C" void kernel_launch(void* const* d_in, const int* in_sizes, int n_in,
                              void* d_out, int out_size)
{
    const float* x    = (const float*)d_in[0];
    const float* cwn  = (const float*)d_in[1];
    const float* b2g  = (const float*)d_in[2];
    const float* b2b  = (const float*)d_in[3];
    const float* b2m  = (const float*)d_in[4];
    const float* b2v  = (const float*)d_in[5];
    const float* cw   = (const float*)d_in[6];
    const float* sc   = (const float*)d_in[7];
    const float* b1g  = (const float*)d_in[8];
    const float* b1b  = (const float*)d_in[9];
    const float* b1m  = (const float*)d_in[10];
    const float* b1v  = (const float*)d_in[11];
    const float* fcw  = (const float*)d_in[12];
    const float* fcb  = (const float*)d_in[13];
    float* out = (float*)d_out;

    const int conv_smem = (2 * ATILE + 2 * BTILE) * 4;
    cudaFuncSetAttribute(k_conv_mma, cudaFuncAttributeMaxDynamicSharedMemorySize,
                         conv_smem);
    const int assign_smem = (128 * FTW + 32 * AWTW + 32 + 32 + 128) * 4;
    cudaFuncSetAttribute(k_assign, cudaFuncAttributeMaxDynamicSharedMemorySize,
                         assign_smem);

    // launch order keeps k_conv_mma at profiled slot (index 3)
    k_zero<<<(BX * KCODES * CCH + 255) / 256, 256>>>();
    k_pre<<<(NW4 + 255) / 256, 256>>>((const float4*)cwn);
    k_cwprep<<<17, 256>>>(cw);

    dim3 g1(NPIX / 128, CCH / 128, BX);
    k_conv_mma<<<g1, 256, conv_smem>>>(x, b2g, b2b, b2m, b2v);

    k_assign<<<BX * (NPIX / 128), 256, assign_smem>>>(sc);

    k_final<<<BX, CCH>>>(cw, b1g, b1b, b1m, b1v, out);

    k_fc<<<BX * CCH / 8, 256>>>(fcw, fcb);

    int n4 = BX * CCH * NPIX / 4;
    k_out<<<n4 / 256, 256>>>((const float4*)x, (float4*)(out + BX * CCH), n4);
}